// round 11
// baseline (speedup 1.0000x reference)
#include <cuda_runtime.h>
#include <cuda_bf16.h>
#include <math.h>

// Problem constants
#define BB 4
#define NN 2048
#define CC 192
#define HH 6
#define DD 32
#define KK 16
#define CH 96          // offset hidden
#define PH 48          // pos hidden
#define ROWS (BB*NN)   // 8192
#define QKVN (3*CC)    // 576

// ---------------- scratch (static device globals; no allocation) ----------------
__device__ float  g_qkv[ROWS * QKVN];      // 18.9 MB
__device__ float  g_h1[ROWS * CH];         // 3.1 MB
__device__ float  g_off[ROWS * 3 * KK];    // 1.57 MB  [B,N,K,3]
__device__ int    g_nn[ROWS * KK];         // nearest indices
__device__ float  g_attn_out[ROWS * CC];   // 6.3 MB

// ---------------- packed f32x2 helpers (Blackwell FFMA2 path) -------------------
// Each half is an independent IEEE fp32 RN op — bitwise identical to the scalar
// __fmaf_rn/__fmul_rn/__fadd_rn chain. Used ONLY to halve instruction count.
typedef unsigned long long ull;
__device__ __forceinline__ ull pk2(float lo, float hi) {
    ull r; asm("mov.b64 %0, {%1, %2};" : "=l"(r) : "f"(lo), "f"(hi)); return r;
}
__device__ __forceinline__ void upk2(ull v, float& lo, float& hi) {
    asm("mov.b64 {%0, %1}, %2;" : "=f"(lo), "=f"(hi) : "l"(v));
}
__device__ __forceinline__ ull fma2(ull a, ull b, ull c) {
    ull r; asm("fma.rn.f32x2 %0, %1, %2, %3;" : "=l"(r) : "l"(a), "l"(b), "l"(c)); return r;
}
__device__ __forceinline__ ull mul2(ull a, ull b) {
    ull r; asm("mul.rn.f32x2 %0, %1, %2;" : "=l"(r) : "l"(a), "l"(b)); return r;
}
__device__ __forceinline__ ull add2(ull a, ull b) {
    ull r; asm("add.rn.f32x2 %0, %1, %2;" : "=l"(r) : "l"(a), "l"(b)); return r;
}

// ---------------- XLA/Eigen-replica erf (f32 rational, clamp [-4,4]) ------------
__device__ __forceinline__ float xla_erf(float x) {
    x = fmaxf(fminf(x, 4.0f), -4.0f);
    float x2 = __fmul_rn(x, x);
    float p = -2.72614225801306e-10f;
    p = __fmaf_rn(p, x2,  2.77068142495902e-08f);
    p = __fmaf_rn(p, x2, -2.10102402082508e-06f);
    p = __fmaf_rn(p, x2, -5.69250639462346e-05f);
    p = __fmaf_rn(p, x2, -7.34990630326855e-04f);
    p = __fmaf_rn(p, x2, -2.95459980854025e-03f);
    p = __fmaf_rn(p, x2, -1.60960333262415e-02f);
    p = __fmul_rn(x, p);
    float q = -1.45660718464996e-05f;
    q = __fmaf_rn(q, x2, -2.13374055278905e-04f);
    q = __fmaf_rn(q, x2, -1.68282697438203e-03f);
    q = __fmaf_rn(q, x2, -7.37332916720468e-03f);
    q = __fmaf_rn(q, x2, -1.42647390514189e-02f);
    return __fdiv_rn(p, q);
}

// jax.nn.gelu(approximate=False) lowering replica
__device__ __forceinline__ float gelu_ref(float x) {
    float t = __fdiv_rn(x, 1.41421356237309504880f);
    float e = xla_erf(t);
    return __fmul_rn(__fmul_rn(x, __fadd_rn(e, 1.0f)), 0.5f);
}

// ---------------- GEMM v2: BM=128, BN=64, BK=16, 256 thr, 8x4 microtile ---------
template<bool GELU>
__global__ void gemm128_kernel(const float* __restrict__ A, const float* __restrict__ B,
                               const float* __restrict__ bias, float* __restrict__ C,
                               int N, int K) {
    __shared__ float As[16][132];
    __shared__ float Bs[16][64];
    const int tid = threadIdx.x;
    const int tx = tid & 15;
    const int ty = tid >> 4;
    const int rowBase = blockIdx.y * 128;
    const int colBase = blockIdx.x * 64;

    float acc[8][4];
#pragma unroll
    for (int i = 0; i < 8; i++)
#pragma unroll
        for (int j = 0; j < 4; j++) acc[i][j] = 0.f;

    for (int k0 = 0; k0 < K; k0 += 16) {
#pragma unroll
        for (int t = 0; t < 8; t++) {
            int idx = tid + t * 256;
            int r = idx >> 4, c = idx & 15;
            As[c][r] = A[(rowBase + r) * K + k0 + c];
        }
#pragma unroll
        for (int t = 0; t < 4; t++) {
            int idx = tid + t * 256;
            int r = idx >> 6, c = idx & 63;
            int col = colBase + c;
            Bs[r][c] = (col < N) ? B[(k0 + r) * N + col] : 0.f;
        }
        __syncthreads();
#pragma unroll
        for (int k = 0; k < 16; k++) {
            float4 a0 = *(const float4*)&As[k][ty * 8];
            float4 a1 = *(const float4*)&As[k][ty * 8 + 4];
            float4 bv4 = *(const float4*)&Bs[k][tx * 4];
            float av[8] = {a0.x, a0.y, a0.z, a0.w, a1.x, a1.y, a1.z, a1.w};
            float bv[4] = {bv4.x, bv4.y, bv4.z, bv4.w};
#pragma unroll
            for (int i = 0; i < 8; i++)
#pragma unroll
                for (int j = 0; j < 4; j++)
                    acc[i][j] = __fmaf_rn(av[i], bv[j], acc[i][j]);
        }
        __syncthreads();
    }
#pragma unroll
    for (int i = 0; i < 8; i++) {
        int row = rowBase + ty * 8 + i;
#pragma unroll
        for (int j = 0; j < 4; j++) {
            int col = colBase + tx * 4 + j;
            if (col < N) {
                float v = __fadd_rn(acc[i][j], bias[col]);
                if (GELU) v = gelu_ref(v);
                C[row * N + col] = v;
            }
        }
    }
}

// ---------------- GEMM 64x64 (kept for the N=48 offset GEMM) -------------------
template<bool GELU>
__global__ void gemm_bias_kernel(const float* __restrict__ A, const float* __restrict__ B,
                                 const float* __restrict__ bias, float* __restrict__ C,
                                 int M, int N, int K) {
    __shared__ float As[16][68];
    __shared__ float Bs[16][64];
    const int tid = threadIdx.x;
    const int tx = tid & 15;
    const int ty = tid >> 4;
    const int rowBase = blockIdx.y * 64;
    const int colBase = blockIdx.x * 64;

    float acc[4][4];
#pragma unroll
    for (int i = 0; i < 4; i++)
#pragma unroll
        for (int j = 0; j < 4; j++) acc[i][j] = 0.f;

    for (int k0 = 0; k0 < K; k0 += 16) {
#pragma unroll
        for (int t = 0; t < 4; t++) {
            int idx = tid + t * 256;
            int r = idx >> 4, c = idx & 15;
            As[c][r] = A[(rowBase + r) * K + k0 + c];
        }
#pragma unroll
        for (int t = 0; t < 4; t++) {
            int idx = tid + t * 256;
            int r = idx >> 6, c = idx & 63;
            int col = colBase + c;
            Bs[r][c] = (col < N) ? B[(k0 + r) * N + col] : 0.f;
        }
        __syncthreads();
#pragma unroll
        for (int k = 0; k < 16; k++) {
            float4 av4 = *(const float4*)&As[k][ty * 4];
            float4 bv4 = *(const float4*)&Bs[k][tx * 4];
            float av[4] = {av4.x, av4.y, av4.z, av4.w};
            float bv[4] = {bv4.x, bv4.y, bv4.z, bv4.w};
#pragma unroll
            for (int i = 0; i < 4; i++)
#pragma unroll
                for (int j = 0; j < 4; j++)
                    acc[i][j] = __fmaf_rn(av[i], bv[j], acc[i][j]);
        }
        __syncthreads();
    }
#pragma unroll
    for (int i = 0; i < 4; i++) {
        int row = rowBase + ty * 4 + i;
#pragma unroll
        for (int j = 0; j < 4; j++) {
            int col = colBase + tx * 4 + j;
            if (col < N) {
                float v = __fadd_rn(acc[i][j], bias[col]);
                if (GELU) v = gelu_ref(v);
                C[row * N + col] = v;
            }
        }
    }
}

// ---------------- nearest neighbor v3: packed f32x2 distance evaluation --------
// Reference-exact d2 rounding per query (DO NOT change the arithmetic):
//   sp  = c + fl(10*o)
//   S   = (sx^2 + sy^2) + sz^2
//   dot = fma(sz,kz, fma(sy,ky, sx*kx))
//   d2  = (S - 2*dot) + C_key
// f32x2 halves are independent RN fp32 ops == the scalar chain bitwise.
// Strict '<' ascending scan == jnp.argmin first-min tie-break.
template<int NPAIR, int NSOLO>
__device__ __forceinline__ void nn_scan2(const ulonglong2* __restrict__ skXY,
                                         const ulonglong2* __restrict__ skZW,
                                         const float* __restrict__ coords,
                                         int b, int base, int lane) {
    ull sx2[NPAIR ? NPAIR : 1], sy2[NPAIR ? NPAIR : 1];
    ull sz2[NPAIR ? NPAIR : 1], S2[NPAIR ? NPAIR : 1];
    float bestA[NPAIR ? NPAIR : 1], bestB[NPAIR ? NPAIR : 1];
    int biA[NPAIR ? NPAIR : 1], biB[NPAIR ? NPAIR : 1];
    float ssx[NSOLO ? NSOLO : 1], ssy[NSOLO ? NSOLO : 1];
    float ssz[NSOLO ? NSOLO : 1], sS[NSOLO ? NSOLO : 1];
    float sbest[NSOLO ? NSOLO : 1];
    int sbi[NSOLO ? NSOLO : 1];

    auto load_q = [&](int q, float& x, float& y, float& z, float& S) {
        int qi = (base + q) * 32 + lane;
        int n = qi >> 4, k = qi & 15;
        const float* cr = coords + (b * NN + n) * 3;
        const float* of = g_off + (b * NN + n) * 48 + k * 3;
        x = __fadd_rn(cr[0], __fmul_rn(of[0], 10.0f));
        y = __fadd_rn(cr[1], __fmul_rn(of[1], 10.0f));
        z = __fadd_rn(cr[2], __fmul_rn(of[2], 10.0f));
        S = __fadd_rn(__fadd_rn(__fmul_rn(x, x), __fmul_rn(y, y)), __fmul_rn(z, z));
    };

#pragma unroll
    for (int p = 0; p < NPAIR; p++) {
        float xa, ya, za, Sa, xb, yb, zb, Sb;
        load_q(2 * p, xa, ya, za, Sa);
        load_q(2 * p + 1, xb, yb, zb, Sb);
        sx2[p] = pk2(xa, xb); sy2[p] = pk2(ya, yb);
        sz2[p] = pk2(za, zb); S2[p] = pk2(Sa, Sb);
        bestA[p] = 3.4e38f; bestB[p] = 3.4e38f; biA[p] = 0; biB[p] = 0;
    }
#pragma unroll
    for (int s = 0; s < NSOLO; s++) {
        load_q(2 * NPAIR + s, ssx[s], ssy[s], ssz[s], sS[s]);
        sbest[s] = 3.4e38f; sbi[s] = 0;
    }

    const ull n2two = pk2(-2.0f, -2.0f);
#pragma unroll 4
    for (int i = 0; i < NN; i++) {
        ulonglong2 xy = skXY[i];     // (x,x),(y,y)
        ulonglong2 zw = skZW[i];     // (z,z),(C,C)
#pragma unroll
        for (int p = 0; p < NPAIR; p++) {
            ull dot = fma2(sz2[p], zw.x, fma2(sy2[p], xy.y, mul2(sx2[p], xy.x)));
            ull d2v = add2(fma2(dot, n2two, S2[p]), zw.y);
            float dlo, dhi; upk2(d2v, dlo, dhi);
            if (dlo < bestA[p]) { bestA[p] = dlo; biA[p] = i; }
            if (dhi < bestB[p]) { bestB[p] = dhi; biB[p] = i; }
        }
#pragma unroll
        for (int s = 0; s < NSOLO; s++) {
            float kx, t0, ky, t1, kz, t2, kw, t3;
            upk2(xy.x, kx, t0); upk2(xy.y, ky, t1);
            upk2(zw.x, kz, t2); upk2(zw.y, kw, t3);
            float dot = __fmaf_rn(ssz[s], kz,
                        __fmaf_rn(ssy[s], ky, __fmul_rn(ssx[s], kx)));
            float d = __fadd_rn(__fmaf_rn(dot, -2.0f, sS[s]), kw);
            if (d < sbest[s]) { sbest[s] = d; sbi[s] = i; }
        }
    }
    int* nnb = g_nn + b * (NN * KK);
#pragma unroll
    for (int p = 0; p < NPAIR; p++) {
        nnb[(base + 2 * p) * 32 + lane] = biA[p];
        nnb[(base + 2 * p + 1) * 32 + lane] = biB[p];
    }
#pragma unroll
    for (int s = 0; s < NSOLO; s++)
        nnb[(base + 2 * NPAIR + s) * 32 + lane] = sbi[s];
}

// grid = (38, BB), 256 threads, 64 KB dynamic smem (duplicated packed keys).
__global__ void nn_kernel(const float* __restrict__ coords) {
    extern __shared__ ulonglong2 skbuf[];   // [0..NN): (xx,yy)   [NN..2NN): (zz,CC)
    const int b = blockIdx.y;
    for (int i = threadIdx.x; i < NN; i += 256) {
        const float* c = coords + (b * NN + i) * 3;
        float x = c[0], y = c[1], z = c[2];
        float s = __fadd_rn(__fadd_rn(__fmul_rn(x, x), __fmul_rn(y, y)), __fmul_rn(z, z));
        ulonglong2 xy, zw;
        xy.x = pk2(x, x); xy.y = pk2(y, y);
        zw.x = pk2(z, z); zw.y = pk2(s, s);
        skbuf[i] = xy;
        skbuf[NN + i] = zw;
    }
    __syncthreads();

    const int w = threadIdx.x >> 5, lane = threadIdx.x & 31;
    const int wib = blockIdx.x * 8 + w;                 // 0..303
    const int base = (wib * 1024) / 304;
    const int nq = ((wib + 1) * 1024) / 304 - base;     // 3 or 4
    if (nq == 4) nn_scan2<2, 0>(skbuf, skbuf + NN, coords, b, base, lane);
    else         nn_scan2<1, 1>(skbuf, skbuf + NN, coords, b, base, lane);
}

// ---------------- attention + pos-bias MLP: one warp per (b,n) ----------------
__global__ void attn_kernel(const float* __restrict__ pos_w1, const float* __restrict__ pos_b1,
                            const float* __restrict__ pos_w2, const float* __restrict__ pos_b2) {
    __shared__ float spw1[144], spb1[48], spw2[288], spb2[8];
    __shared__ float shid[8][768];
    __shared__ float sbias[8][96];
    __shared__ float soff[8][48];
    __shared__ int   snn[8][16];

    const int tid = threadIdx.x;
    for (int i = tid; i < 144; i += 256) spw1[i] = pos_w1[i];
    for (int i = tid; i < 48;  i += 256) spb1[i] = pos_b1[i];
    for (int i = tid; i < 288; i += 256) spw2[i] = pos_w2[i];
    if (tid < 6) spb2[tid] = pos_b2[tid];
    __syncthreads();

    const int w = tid >> 5, lane = tid & 31;
    const int gw = blockIdx.x * 8 + w;      // 0..8191
    const int b = gw >> 11, n = gw & 2047;
    const int row = b * NN + n;

    for (int t = lane; t < 48; t += 32) soff[w][t] = g_off[row * 48 + t];
    if (lane < 16) snn[w][lane] = g_nn[row * 16 + lane];
    __syncwarp();

#pragma unroll 4
    for (int t = 0; t < 24; t++) {
        int idx = t * 32 + lane;
        int k = idx / 48, j = idx - k * 48;
        float o0 = soff[w][k * 3 + 0];
        float o1 = soff[w][k * 3 + 1];
        float o2 = soff[w][k * 3 + 2];
        float hv = __fmaf_rn(o0, spw1[j], spb1[j]);
        hv = __fmaf_rn(o1, spw1[48 + j], hv);
        hv = __fmaf_rn(o2, spw1[96 + j], hv);
        shid[w][k * 48 + j] = gelu_ref(hv);
    }
    __syncwarp();

#pragma unroll
    for (int t = 0; t < 3; t++) {
        int idx = t * 32 + lane;
        int k = idx / 6, h = idx - k * 6;
        float s = spb2[h];
#pragma unroll 8
        for (int j = 0; j < 48; j++)
            s = __fmaf_rn(shid[w][k * 48 + j], spw2[j * 6 + h], s);
        sbias[w][idx] = s;
    }
    __syncwarp();

    const float* qrow = g_qkv + (size_t)row * QKVN;
    float* orow = g_attn_out + (size_t)row * CC;
    const unsigned FULL = 0xffffffffu;

    for (int h = 0; h < HH; h++) {
        float qd = qrow[h * DD + lane];
        float lk = 0.f;
#pragma unroll
        for (int k = 0; k < KK; k++) {
            int nk = snn[w][k];
            float kv = g_qkv[(size_t)(b * NN + nk) * QKVN + CC + h * DD + lane];
            float p = qd * kv;
            p += __shfl_xor_sync(FULL, p, 16);
            p += __shfl_xor_sync(FULL, p, 8);
            p += __shfl_xor_sync(FULL, p, 4);
            p += __shfl_xor_sync(FULL, p, 2);
            p += __shfl_xor_sync(FULL, p, 1);
            if (lane == k) lk = p;
        }
        float logit = (lane < KK)
                      ? (lk * 0.17677669529663687f + sbias[w][lane * 6 + h])
                      : -1e30f;
        float m = logit;
        m = fmaxf(m, __shfl_xor_sync(FULL, m, 8));
        m = fmaxf(m, __shfl_xor_sync(FULL, m, 4));
        m = fmaxf(m, __shfl_xor_sync(FULL, m, 2));
        m = fmaxf(m, __shfl_xor_sync(FULL, m, 1));
        float e = (lane < KK) ? expf(logit - m) : 0.f;
        float s = e;
        s += __shfl_xor_sync(FULL, s, 8);
        s += __shfl_xor_sync(FULL, s, 4);
        s += __shfl_xor_sync(FULL, s, 2);
        s += __shfl_xor_sync(FULL, s, 1);
        float a = e / s;
        float od = 0.f;
#pragma unroll
        for (int k = 0; k < KK; k++) {
            float ak = __shfl_sync(FULL, a, k);
            int nk = snn[w][k];
            float vv = g_qkv[(size_t)(b * NN + nk) * QKVN + 2 * CC + h * DD + lane];
            od = __fmaf_rn(ak, vv, od);
        }
        orow[h * DD + lane] = od;
    }
}

// ---------------- launch ----------------
extern "C" void kernel_launch(void* const* d_in, const int* in_sizes, int n_in,
                              void* d_out, int out_size) {
    const float* coords  = (const float*)d_in[0];
    const float* x       = (const float*)d_in[1];
    const float* qkv_w   = (const float*)d_in[2];
    const float* qkv_b   = (const float*)d_in[3];
    const float* proj_w  = (const float*)d_in[4];
    const float* proj_b  = (const float*)d_in[5];
    const float* off_w1  = (const float*)d_in[6];
    const float* off_b1  = (const float*)d_in[7];
    const float* off_w2  = (const float*)d_in[8];
    const float* off_b2  = (const float*)d_in[9];
    const float* pos_w1  = (const float*)d_in[10];
    const float* pos_b1  = (const float*)d_in[11];
    const float* pos_w2  = (const float*)d_in[12];
    const float* pos_b2  = (const float*)d_in[13];
    float* out = (float*)d_out;

    float *qkv_p, *h1_p, *off_p, *att_p;
    cudaGetSymbolAddress((void**)&qkv_p, g_qkv);
    cudaGetSymbolAddress((void**)&h1_p,  g_h1);
    cudaGetSymbolAddress((void**)&off_p, g_off);
    cudaGetSymbolAddress((void**)&att_p, g_attn_out);

    // allow 64 KB dynamic smem for nn_kernel (idempotent)
    cudaFuncSetAttribute(nn_kernel, cudaFuncAttributeMaxDynamicSharedMemorySize, 65536);

    // 1) qkv = x @ qkv_w + qkv_b    [8192,576]
    gemm128_kernel<false><<<dim3(QKVN / 64, ROWS / 128), 256>>>(
        x, qkv_w, qkv_b, qkv_p, QKVN, CC);

    // 2) h1 = gelu(x @ off_w1 + off_b1)   [8192,96]
    gemm128_kernel<true><<<dim3(2, ROWS / 128), 256>>>(
        x, off_w1, off_b1, h1_p, CH, CC);

    // 3) offsets = h1 @ off_w2 + off_b2   [8192,48]
    gemm_bias_kernel<false><<<dim3(1, ROWS / 64), 256>>>(
        h1_p, off_w2, off_b2, off_p, ROWS, 3 * KK, CH);

    // 4) nearest-neighbor argmin (packed f32x2 distance eval)
    nn_kernel<<<dim3(38, BB), 256, 65536>>>(coords);

    // 5) attention + positional bias
    attn_kernel<<<ROWS / 8, 256>>>(pos_w1, pos_b1, pos_w2, pos_b2);

    // 6) out = attn_out @ proj_w + proj_b   [8192,192]
    gemm128_kernel<false><<<dim3(CC / 64, ROWS / 128), 256>>>(
        att_p, proj_w, proj_b, out, CC, CC);
}

// round 12
// speedup vs baseline: 1.1254x; 1.1254x over previous
#include <cuda_runtime.h>
#include <cuda_bf16.h>
#include <math.h>

// Problem constants
#define BB 4
#define NN 2048
#define CC 192
#define HH 6
#define DD 32
#define KK 16
#define CH 96          // offset hidden
#define PH 48          // pos hidden
#define ROWS (BB*NN)   // 8192
#define QKVN (3*CC)    // 576

// ---------------- scratch (static device globals; no allocation) ----------------
__device__ float  g_qkv[ROWS * QKVN];      // 18.9 MB
__device__ float  g_h1[ROWS * CH];         // 3.1 MB
__device__ float  g_off[ROWS * 3 * KK];    // 1.57 MB  [B,N,K,3]
__device__ int    g_nn[ROWS * KK];         // nearest indices
__device__ float  g_attn_out[ROWS * CC];   // 6.3 MB

// ---------------- XLA/Eigen-replica erf (f32 rational, clamp [-4,4]) ------------
__device__ __forceinline__ float xla_erf(float x) {
    x = fmaxf(fminf(x, 4.0f), -4.0f);
    float x2 = __fmul_rn(x, x);
    float p = -2.72614225801306e-10f;
    p = __fmaf_rn(p, x2,  2.77068142495902e-08f);
    p = __fmaf_rn(p, x2, -2.10102402082508e-06f);
    p = __fmaf_rn(p, x2, -5.69250639462346e-05f);
    p = __fmaf_rn(p, x2, -7.34990630326855e-04f);
    p = __fmaf_rn(p, x2, -2.95459980854025e-03f);
    p = __fmaf_rn(p, x2, -1.60960333262415e-02f);
    p = __fmul_rn(x, p);
    float q = -1.45660718464996e-05f;
    q = __fmaf_rn(q, x2, -2.13374055278905e-04f);
    q = __fmaf_rn(q, x2, -1.68282697438203e-03f);
    q = __fmaf_rn(q, x2, -7.37332916720468e-03f);
    q = __fmaf_rn(q, x2, -1.42647390514189e-02f);
    return __fdiv_rn(p, q);
}

// jax.nn.gelu(approximate=False) lowering replica
__device__ __forceinline__ float gelu_ref(float x) {
    float t = __fdiv_rn(x, 1.41421356237309504880f);
    float e = xla_erf(t);
    return __fmul_rn(__fmul_rn(x, __fadd_rn(e, 1.0f)), 0.5f);
}

// ---------------- GEMM v2: BM=128, BN=64, BK=16, 256 thr, 8x4 microtile ---------
template<bool GELU>
__global__ void gemm128_kernel(const float* __restrict__ A, const float* __restrict__ B,
                               const float* __restrict__ bias, float* __restrict__ C,
                               int N, int K) {
    __shared__ float As[16][132];
    __shared__ float Bs[16][64];
    const int tid = threadIdx.x;
    const int tx = tid & 15;
    const int ty = tid >> 4;
    const int rowBase = blockIdx.y * 128;
    const int colBase = blockIdx.x * 64;

    float acc[8][4];
#pragma unroll
    for (int i = 0; i < 8; i++)
#pragma unroll
        for (int j = 0; j < 4; j++) acc[i][j] = 0.f;

    for (int k0 = 0; k0 < K; k0 += 16) {
#pragma unroll
        for (int t = 0; t < 8; t++) {
            int idx = tid + t * 256;
            int r = idx >> 4, c = idx & 15;
            As[c][r] = A[(rowBase + r) * K + k0 + c];
        }
#pragma unroll
        for (int t = 0; t < 4; t++) {
            int idx = tid + t * 256;
            int r = idx >> 6, c = idx & 63;
            int col = colBase + c;
            Bs[r][c] = (col < N) ? B[(k0 + r) * N + col] : 0.f;
        }
        __syncthreads();
#pragma unroll
        for (int k = 0; k < 16; k++) {
            float4 a0 = *(const float4*)&As[k][ty * 8];
            float4 a1 = *(const float4*)&As[k][ty * 8 + 4];
            float4 bv4 = *(const float4*)&Bs[k][tx * 4];
            float av[8] = {a0.x, a0.y, a0.z, a0.w, a1.x, a1.y, a1.z, a1.w};
            float bv[4] = {bv4.x, bv4.y, bv4.z, bv4.w};
#pragma unroll
            for (int i = 0; i < 8; i++)
#pragma unroll
                for (int j = 0; j < 4; j++)
                    acc[i][j] = __fmaf_rn(av[i], bv[j], acc[i][j]);
        }
        __syncthreads();
    }
#pragma unroll
    for (int i = 0; i < 8; i++) {
        int row = rowBase + ty * 8 + i;
#pragma unroll
        for (int j = 0; j < 4; j++) {
            int col = colBase + tx * 4 + j;
            if (col < N) {
                float v = __fadd_rn(acc[i][j], bias[col]);
                if (GELU) v = gelu_ref(v);
                C[row * N + col] = v;
            }
        }
    }
}

// ---------------- GEMM 64x64 (kept for the N=48 offset GEMM) -------------------
template<bool GELU>
__global__ void gemm_bias_kernel(const float* __restrict__ A, const float* __restrict__ B,
                                 const float* __restrict__ bias, float* __restrict__ C,
                                 int M, int N, int K) {
    __shared__ float As[16][68];
    __shared__ float Bs[16][64];
    const int tid = threadIdx.x;
    const int tx = tid & 15;
    const int ty = tid >> 4;
    const int rowBase = blockIdx.y * 64;
    const int colBase = blockIdx.x * 64;

    float acc[4][4];
#pragma unroll
    for (int i = 0; i < 4; i++)
#pragma unroll
        for (int j = 0; j < 4; j++) acc[i][j] = 0.f;

    for (int k0 = 0; k0 < K; k0 += 16) {
#pragma unroll
        for (int t = 0; t < 4; t++) {
            int idx = tid + t * 256;
            int r = idx >> 4, c = idx & 15;
            As[c][r] = A[(rowBase + r) * K + k0 + c];
        }
#pragma unroll
        for (int t = 0; t < 4; t++) {
            int idx = tid + t * 256;
            int r = idx >> 6, c = idx & 63;
            int col = colBase + c;
            Bs[r][c] = (col < N) ? B[(k0 + r) * N + col] : 0.f;
        }
        __syncthreads();
#pragma unroll
        for (int k = 0; k < 16; k++) {
            float4 av4 = *(const float4*)&As[k][ty * 4];
            float4 bv4 = *(const float4*)&Bs[k][tx * 4];
            float av[4] = {av4.x, av4.y, av4.z, av4.w};
            float bv[4] = {bv4.x, bv4.y, bv4.z, bv4.w};
#pragma unroll
            for (int i = 0; i < 4; i++)
#pragma unroll
                for (int j = 0; j < 4; j++)
                    acc[i][j] = __fmaf_rn(av[i], bv[j], acc[i][j]);
        }
        __syncthreads();
    }
#pragma unroll
    for (int i = 0; i < 4; i++) {
        int row = rowBase + ty * 4 + i;
#pragma unroll
        for (int j = 0; j < 4; j++) {
            int col = colBase + tx * 4 + j;
            if (col < N) {
                float v = __fadd_rn(acc[i][j], bias[col]);
                if (GELU) v = gelu_ref(v);
                C[row * N + col] = v;
            }
        }
    }
}

// ---------------- nearest neighbor (R10 scalar version — proven fastest) -------
// Reference-exact d2 rounding (DO NOT change the arithmetic):
//   sp  = c + fl(10*o)
//   S   = (sx^2 + sy^2) + sz^2
//   dot = fma(sz,kz, fma(sy,ky, sx*kx))
//   d2  = (S - 2*dot) + C_key
// Strict '<' ascending scan == jnp.argmin first-min tie-break.
template<int NQ>
__device__ __forceinline__ void nn_scan(const float4* __restrict__ sk,
                                        const float* __restrict__ coords,
                                        int b, int base, int lane) {
    float sx[NQ], sy[NQ], sz[NQ], S[NQ], best[NQ];
    int bi[NQ], qidx[NQ];
#pragma unroll
    for (int q = 0; q < NQ; q++) {
        int qi = (base + q) * 32 + lane;          // 0..32767 within batch
        qidx[q] = qi;
        int n = qi >> 4, k = qi & 15;
        const float* cr = coords + (b * NN + n) * 3;
        const float* of = g_off + (b * NN + n) * 48 + k * 3;
        sx[q] = __fadd_rn(cr[0], __fmul_rn(of[0], 10.0f));
        sy[q] = __fadd_rn(cr[1], __fmul_rn(of[1], 10.0f));
        sz[q] = __fadd_rn(cr[2], __fmul_rn(of[2], 10.0f));
        S[q]  = __fadd_rn(__fadd_rn(__fmul_rn(sx[q], sx[q]), __fmul_rn(sy[q], sy[q])),
                          __fmul_rn(sz[q], sz[q]));
        best[q] = 3.4e38f;
        bi[q] = 0;
    }
#pragma unroll 4
    for (int i = 0; i < NN; i++) {
        float4 kk = sk[i];
#pragma unroll
        for (int q = 0; q < NQ; q++) {
            float dot = __fmaf_rn(sz[q], kk.z,
                        __fmaf_rn(sy[q], kk.y, __fmul_rn(sx[q], kk.x)));
            float d = __fadd_rn(__fmaf_rn(dot, -2.0f, S[q]), kk.w);
            if (d < best[q]) { best[q] = d; bi[q] = i; }
        }
    }
#pragma unroll
    for (int q = 0; q < NQ; q++)
        g_nn[b * (NN * KK) + qidx[q]] = bi[q];
}

// grid = (38, BB), 256 threads. 304 warps per batch cover 1024 chunks of 32
// queries via Bresenham assignment. Key packing fused into the kernel.
__global__ void nn_kernel(const float* __restrict__ coords) {
    __shared__ float4 sk[NN];   // 32 KB
    const int b = blockIdx.y;
    for (int i = threadIdx.x; i < NN; i += 256) {
        const float* c = coords + (b * NN + i) * 3;
        float x = c[0], y = c[1], z = c[2];
        float s = __fadd_rn(__fadd_rn(__fmul_rn(x, x), __fmul_rn(y, y)), __fmul_rn(z, z));
        sk[i] = make_float4(x, y, z, s);
    }
    __syncthreads();

    const int w = threadIdx.x >> 5, lane = threadIdx.x & 31;
    const int wib = blockIdx.x * 8 + w;                 // 0..303
    const int base = (wib * 1024) / 304;
    const int nq = ((wib + 1) * 1024) / 304 - base;     // 3 or 4
    if (nq == 4) nn_scan<4>(sk, coords, b, base, lane);
    else         nn_scan<3>(sk, coords, b, base, lane);
}

// ---------------- attention + pos-bias MLP: one warp per (b,n) ----------------
__global__ void attn_kernel(const float* __restrict__ pos_w1, const float* __restrict__ pos_b1,
                            const float* __restrict__ pos_w2, const float* __restrict__ pos_b2) {
    __shared__ float spw1[144], spb1[48], spw2[288], spb2[8];
    __shared__ float shid[8][768];
    __shared__ float sbias[8][96];
    __shared__ float soff[8][48];
    __shared__ int   snn[8][16];

    const int tid = threadIdx.x;
    for (int i = tid; i < 144; i += 256) spw1[i] = pos_w1[i];
    for (int i = tid; i < 48;  i += 256) spb1[i] = pos_b1[i];
    for (int i = tid; i < 288; i += 256) spw2[i] = pos_w2[i];
    if (tid < 6) spb2[tid] = pos_b2[tid];
    __syncthreads();

    const int w = tid >> 5, lane = tid & 31;
    const int gw = blockIdx.x * 8 + w;      // 0..8191
    const int b = gw >> 11, n = gw & 2047;
    const int row = b * NN + n;

    for (int t = lane; t < 48; t += 32) soff[w][t] = g_off[row * 48 + t];
    if (lane < 16) snn[w][lane] = g_nn[row * 16 + lane];
    __syncwarp();

#pragma unroll 4
    for (int t = 0; t < 24; t++) {
        int idx = t * 32 + lane;
        int k = idx / 48, j = idx - k * 48;
        float o0 = soff[w][k * 3 + 0];
        float o1 = soff[w][k * 3 + 1];
        float o2 = soff[w][k * 3 + 2];
        float hv = __fmaf_rn(o0, spw1[j], spb1[j]);
        hv = __fmaf_rn(o1, spw1[48 + j], hv);
        hv = __fmaf_rn(o2, spw1[96 + j], hv);
        shid[w][k * 48 + j] = gelu_ref(hv);
    }
    __syncwarp();

#pragma unroll
    for (int t = 0; t < 3; t++) {
        int idx = t * 32 + lane;
        int k = idx / 6, h = idx - k * 6;
        float s = spb2[h];
#pragma unroll 8
        for (int j = 0; j < 48; j++)
            s = __fmaf_rn(shid[w][k * 48 + j], spw2[j * 6 + h], s);
        sbias[w][idx] = s;
    }
    __syncwarp();

    const float* qrow = g_qkv + (size_t)row * QKVN;
    float* orow = g_attn_out + (size_t)row * CC;
    const unsigned FULL = 0xffffffffu;

    for (int h = 0; h < HH; h++) {
        float qd = qrow[h * DD + lane];
        float lk = 0.f;
#pragma unroll
        for (int k = 0; k < KK; k++) {
            int nk = snn[w][k];
            float kv = g_qkv[(size_t)(b * NN + nk) * QKVN + CC + h * DD + lane];
            float p = qd * kv;
            p += __shfl_xor_sync(FULL, p, 16);
            p += __shfl_xor_sync(FULL, p, 8);
            p += __shfl_xor_sync(FULL, p, 4);
            p += __shfl_xor_sync(FULL, p, 2);
            p += __shfl_xor_sync(FULL, p, 1);
            if (lane == k) lk = p;
        }
        float logit = (lane < KK)
                      ? (lk * 0.17677669529663687f + sbias[w][lane * 6 + h])
                      : -1e30f;
        float m = logit;
        m = fmaxf(m, __shfl_xor_sync(FULL, m, 8));
        m = fmaxf(m, __shfl_xor_sync(FULL, m, 4));
        m = fmaxf(m, __shfl_xor_sync(FULL, m, 2));
        m = fmaxf(m, __shfl_xor_sync(FULL, m, 1));
        float e = (lane < KK) ? expf(logit - m) : 0.f;
        float s = e;
        s += __shfl_xor_sync(FULL, s, 8);
        s += __shfl_xor_sync(FULL, s, 4);
        s += __shfl_xor_sync(FULL, s, 2);
        s += __shfl_xor_sync(FULL, s, 1);
        float a = e / s;
        float od = 0.f;
#pragma unroll
        for (int k = 0; k < KK; k++) {
            float ak = __shfl_sync(FULL, a, k);
            int nk = snn[w][k];
            float vv = g_qkv[(size_t)(b * NN + nk) * QKVN + 2 * CC + h * DD + lane];
            od = __fmaf_rn(ak, vv, od);
        }
        orow[h * DD + lane] = od;
    }
}

// ---------------- launch (forked capture: qkv ∥ {h1→off→NN}) -------------------
extern "C" void kernel_launch(void* const* d_in, const int* in_sizes, int n_in,
                              void* d_out, int out_size) {
    const float* coords  = (const float*)d_in[0];
    const float* x       = (const float*)d_in[1];
    const float* qkv_w   = (const float*)d_in[2];
    const float* qkv_b   = (const float*)d_in[3];
    const float* proj_w  = (const float*)d_in[4];
    const float* proj_b  = (const float*)d_in[5];
    const float* off_w1  = (const float*)d_in[6];
    const float* off_b1  = (const float*)d_in[7];
    const float* off_w2  = (const float*)d_in[8];
    const float* off_b2  = (const float*)d_in[9];
    const float* pos_w1  = (const float*)d_in[10];
    const float* pos_b1  = (const float*)d_in[11];
    const float* pos_w2  = (const float*)d_in[12];
    const float* pos_b2  = (const float*)d_in[13];
    float* out = (float*)d_out;

    float *qkv_p, *h1_p, *off_p, *att_p;
    cudaGetSymbolAddress((void**)&qkv_p, g_qkv);
    cudaGetSymbolAddress((void**)&h1_p,  g_h1);
    cudaGetSymbolAddress((void**)&off_p, g_off);
    cudaGetSymbolAddress((void**)&att_p, g_attn_out);

    // Lazily-created side stream + fork/join events (host-side objects only;
    // created on the uncaptured correctness call, reused identically by capture).
    static cudaStream_t s_side = nullptr;
    static cudaEvent_t  s_fork = nullptr, s_join = nullptr;
    if (s_side == nullptr) {
        cudaStreamCreateWithFlags(&s_side, cudaStreamNonBlocking);
        cudaEventCreateWithFlags(&s_fork, cudaEventDisableTiming);
        cudaEventCreateWithFlags(&s_join, cudaEventDisableTiming);
    }

    // fork: side stream inherits capture state from the main (default) stream
    cudaEventRecord(s_fork, (cudaStream_t)0);
    cudaStreamWaitEvent(s_side, s_fork, 0);

    // -- branch B (side stream): qkv = x @ qkv_w + qkv_b   [8192,576]
    gemm128_kernel<false><<<dim3(QKVN / 64, ROWS / 128), 256, 0, s_side>>>(
        x, qkv_w, qkv_b, qkv_p, QKVN, CC);

    // -- branch A (main stream): offset net + NN
    // h1 = gelu(x @ off_w1 + off_b1)   [8192,96]
    gemm128_kernel<true><<<dim3(2, ROWS / 128), 256>>>(
        x, off_w1, off_b1, h1_p, CH, CC);
    // offsets = h1 @ off_w2 + off_b2   [8192,48]
    gemm_bias_kernel<false><<<dim3(1, ROWS / 64), 256>>>(
        h1_p, off_w2, off_b2, off_p, ROWS, 3 * KK, CH);
    // nearest-neighbor argmin
    nn_kernel<<<dim3(38, BB), 256>>>(coords);

    // join: attn needs qkv (branch B) and NN (branch A)
    cudaEventRecord(s_join, s_side);
    cudaStreamWaitEvent((cudaStream_t)0, s_join, 0);

    // attention + positional bias
    attn_kernel<<<ROWS / 8, 256>>>(pos_w1, pos_b1, pos_w2, pos_b2);

    // out = attn_out @ proj_w + proj_b   [8192,192]
    gemm128_kernel<false><<<dim3(CC / 64, ROWS / 128), 256>>>(
        att_p, proj_w, proj_b, out, CC, CC);
}

// round 13
// speedup vs baseline: 1.1285x; 1.0028x over previous
#include <cuda_runtime.h>
#include <cuda_bf16.h>
#include <math.h>

// Problem constants
#define BB 4
#define NN 2048
#define CC 192
#define HH 6
#define DD 32
#define KK 16
#define CH 96          // offset hidden
#define PH 48          // pos hidden
#define ROWS (BB*NN)   // 8192
#define QKVN (3*CC)    // 576

// ---------------- scratch (static device globals; no allocation) ----------------
__device__ float  g_qkv[ROWS * QKVN];      // 18.9 MB
__device__ float  g_h1[ROWS * CH];         // 3.1 MB
__device__ float  g_off[ROWS * 3 * KK];    // 1.57 MB  [B,N,K,3]
__device__ int    g_nn[ROWS * KK];         // nearest indices
__device__ float  g_attn_out[ROWS * CC];   // 6.3 MB

// ---------------- XLA/Eigen-replica erf (f32 rational, clamp [-4,4]) ------------
__device__ __forceinline__ float xla_erf(float x) {
    x = fmaxf(fminf(x, 4.0f), -4.0f);
    float x2 = __fmul_rn(x, x);
    float p = -2.72614225801306e-10f;
    p = __fmaf_rn(p, x2,  2.77068142495902e-08f);
    p = __fmaf_rn(p, x2, -2.10102402082508e-06f);
    p = __fmaf_rn(p, x2, -5.69250639462346e-05f);
    p = __fmaf_rn(p, x2, -7.34990630326855e-04f);
    p = __fmaf_rn(p, x2, -2.95459980854025e-03f);
    p = __fmaf_rn(p, x2, -1.60960333262415e-02f);
    p = __fmul_rn(x, p);
    float q = -1.45660718464996e-05f;
    q = __fmaf_rn(q, x2, -2.13374055278905e-04f);
    q = __fmaf_rn(q, x2, -1.68282697438203e-03f);
    q = __fmaf_rn(q, x2, -7.37332916720468e-03f);
    q = __fmaf_rn(q, x2, -1.42647390514189e-02f);
    return __fdiv_rn(p, q);
}

// jax.nn.gelu(approximate=False) lowering replica
__device__ __forceinline__ float gelu_ref(float x) {
    float t = __fdiv_rn(x, 1.41421356237309504880f);
    float e = xla_erf(t);
    return __fmul_rn(__fmul_rn(x, __fadd_rn(e, 1.0f)), 0.5f);
}

// ---------------- GEMM v2: BM=128, BN=64, BK=16, 256 thr, 8x4 microtile ---------
template<bool GELU>
__global__ void gemm128_kernel(const float* __restrict__ A, const float* __restrict__ B,
                               const float* __restrict__ bias, float* __restrict__ C,
                               int N, int K) {
    __shared__ float As[16][132];
    __shared__ float Bs[16][64];
    const int tid = threadIdx.x;
    const int tx = tid & 15;
    const int ty = tid >> 4;
    const int rowBase = blockIdx.y * 128;
    const int colBase = blockIdx.x * 64;

    float acc[8][4];
#pragma unroll
    for (int i = 0; i < 8; i++)
#pragma unroll
        for (int j = 0; j < 4; j++) acc[i][j] = 0.f;

    for (int k0 = 0; k0 < K; k0 += 16) {
#pragma unroll
        for (int t = 0; t < 8; t++) {
            int idx = tid + t * 256;
            int r = idx >> 4, c = idx & 15;
            As[c][r] = A[(rowBase + r) * K + k0 + c];
        }
#pragma unroll
        for (int t = 0; t < 4; t++) {
            int idx = tid + t * 256;
            int r = idx >> 6, c = idx & 63;
            int col = colBase + c;
            Bs[r][c] = (col < N) ? B[(k0 + r) * N + col] : 0.f;
        }
        __syncthreads();
#pragma unroll
        for (int k = 0; k < 16; k++) {
            float4 a0 = *(const float4*)&As[k][ty * 8];
            float4 a1 = *(const float4*)&As[k][ty * 8 + 4];
            float4 bv4 = *(const float4*)&Bs[k][tx * 4];
            float av[8] = {a0.x, a0.y, a0.z, a0.w, a1.x, a1.y, a1.z, a1.w};
            float bv[4] = {bv4.x, bv4.y, bv4.z, bv4.w};
#pragma unroll
            for (int i = 0; i < 8; i++)
#pragma unroll
                for (int j = 0; j < 4; j++)
                    acc[i][j] = __fmaf_rn(av[i], bv[j], acc[i][j]);
        }
        __syncthreads();
    }
#pragma unroll
    for (int i = 0; i < 8; i++) {
        int row = rowBase + ty * 8 + i;
#pragma unroll
        for (int j = 0; j < 4; j++) {
            int col = colBase + tx * 4 + j;
            if (col < N) {
                float v = __fadd_rn(acc[i][j], bias[col]);
                if (GELU) v = gelu_ref(v);
                C[row * N + col] = v;
            }
        }
    }
}

// ---------------- GEMM 64x64 (kept for the N=48 offset GEMM) -------------------
template<bool GELU>
__global__ void gemm_bias_kernel(const float* __restrict__ A, const float* __restrict__ B,
                                 const float* __restrict__ bias, float* __restrict__ C,
                                 int M, int N, int K) {
    __shared__ float As[16][68];
    __shared__ float Bs[16][64];
    const int tid = threadIdx.x;
    const int tx = tid & 15;
    const int ty = tid >> 4;
    const int rowBase = blockIdx.y * 64;
    const int colBase = blockIdx.x * 64;

    float acc[4][4];
#pragma unroll
    for (int i = 0; i < 4; i++)
#pragma unroll
        for (int j = 0; j < 4; j++) acc[i][j] = 0.f;

    for (int k0 = 0; k0 < K; k0 += 16) {
#pragma unroll
        for (int t = 0; t < 4; t++) {
            int idx = tid + t * 256;
            int r = idx >> 4, c = idx & 15;
            As[c][r] = A[(rowBase + r) * K + k0 + c];
        }
#pragma unroll
        for (int t = 0; t < 4; t++) {
            int idx = tid + t * 256;
            int r = idx >> 6, c = idx & 63;
            int col = colBase + c;
            Bs[r][c] = (col < N) ? B[(k0 + r) * N + col] : 0.f;
        }
        __syncthreads();
#pragma unroll
        for (int k = 0; k < 16; k++) {
            float4 av4 = *(const float4*)&As[k][ty * 4];
            float4 bv4 = *(const float4*)&Bs[k][tx * 4];
            float av[4] = {av4.x, av4.y, av4.z, av4.w};
            float bv[4] = {bv4.x, bv4.y, bv4.z, bv4.w};
#pragma unroll
            for (int i = 0; i < 4; i++)
#pragma unroll
                for (int j = 0; j < 4; j++)
                    acc[i][j] = __fmaf_rn(av[i], bv[j], acc[i][j]);
        }
        __syncthreads();
    }
#pragma unroll
    for (int i = 0; i < 4; i++) {
        int row = rowBase + ty * 4 + i;
#pragma unroll
        for (int j = 0; j < 4; j++) {
            int col = colBase + tx * 4 + j;
            if (col < N) {
                float v = __fadd_rn(acc[i][j], bias[col]);
                if (GELU) v = gelu_ref(v);
                C[row * N + col] = v;
            }
        }
    }
}

// ---------------- nearest neighbor v4: 512 thr/block, 16 warps/SM ---------------
// Reference-exact d2 rounding (DO NOT change the arithmetic):
//   sp  = c + fl(10*o)
//   S   = (sx^2 + sy^2) + sz^2
//   dot = fma(sz,kz, fma(sy,ky, sx*kx))
//   d2  = (S - 2*dot) + C_key
// Strict '<' ascending scan == jnp.argmin first-min tie-break.
template<int NQ>
__device__ __forceinline__ void nn_scan(const float4* __restrict__ sk,
                                        const float* __restrict__ coords,
                                        int b, int base, int lane) {
    float sx[NQ], sy[NQ], sz[NQ], S[NQ], best[NQ];
    int bi[NQ], qidx[NQ];
#pragma unroll
    for (int q = 0; q < NQ; q++) {
        int qi = (base + q) * 32 + lane;          // 0..32767 within batch
        qidx[q] = qi;
        int n = qi >> 4, k = qi & 15;
        const float* cr = coords + (b * NN + n) * 3;
        const float* of = g_off + (b * NN + n) * 48 + k * 3;
        sx[q] = __fadd_rn(cr[0], __fmul_rn(of[0], 10.0f));
        sy[q] = __fadd_rn(cr[1], __fmul_rn(of[1], 10.0f));
        sz[q] = __fadd_rn(cr[2], __fmul_rn(of[2], 10.0f));
        S[q]  = __fadd_rn(__fadd_rn(__fmul_rn(sx[q], sx[q]), __fmul_rn(sy[q], sy[q])),
                          __fmul_rn(sz[q], sz[q]));
        best[q] = 3.4e38f;
        bi[q] = 0;
    }
#pragma unroll 8
    for (int i = 0; i < NN; i++) {
        float4 kk = sk[i];
#pragma unroll
        for (int q = 0; q < NQ; q++) {
            float dot = __fmaf_rn(sz[q], kk.z,
                        __fmaf_rn(sy[q], kk.y, __fmul_rn(sx[q], kk.x)));
            float d = __fadd_rn(__fmaf_rn(dot, -2.0f, S[q]), kk.w);
            if (d < best[q]) { best[q] = d; bi[q] = i; }
        }
    }
#pragma unroll
    for (int q = 0; q < NQ; q++)
        g_nn[b * (NN * KK) + qidx[q]] = bi[q];
}

// grid = (38, BB), 512 threads (16 warps/block, 1 block/SM -> 4 warps/SMSP).
// 608 warps per batch cover 1024 chunks of 32 queries via Bresenham (1 or 2
// chunks per warp). Key packing fused into the kernel; one 32 KB key copy/SM.
__global__ void __launch_bounds__(512, 1) nn_kernel(const float* __restrict__ coords) {
    __shared__ float4 sk[NN];   // 32 KB
    const int b = blockIdx.y;
    for (int i = threadIdx.x; i < NN; i += 512) {
        const float* c = coords + (b * NN + i) * 3;
        float x = c[0], y = c[1], z = c[2];
        float s = __fadd_rn(__fadd_rn(__fmul_rn(x, x), __fmul_rn(y, y)), __fmul_rn(z, z));
        sk[i] = make_float4(x, y, z, s);
    }
    __syncthreads();

    const int w = threadIdx.x >> 5, lane = threadIdx.x & 31;
    const int wib = blockIdx.x * 16 + w;                // 0..607
    const int base = (wib * 1024) / 608;
    const int nq = ((wib + 1) * 1024) / 608 - base;     // 1 or 2
    if (nq == 2) nn_scan<2>(sk, coords, b, base, lane);
    else         nn_scan<1>(sk, coords, b, base, lane);
}

// ---------------- attention + pos-bias MLP: one warp per (b,n) ----------------
__global__ void attn_kernel(const float* __restrict__ pos_w1, const float* __restrict__ pos_b1,
                            const float* __restrict__ pos_w2, const float* __restrict__ pos_b2) {
    __shared__ float spw1[144], spb1[48], spw2[288], spb2[8];
    __shared__ float shid[8][768];
    __shared__ float sbias[8][96];
    __shared__ float soff[8][48];
    __shared__ int   snn[8][16];

    const int tid = threadIdx.x;
    for (int i = tid; i < 144; i += 256) spw1[i] = pos_w1[i];
    for (int i = tid; i < 48;  i += 256) spb1[i] = pos_b1[i];
    for (int i = tid; i < 288; i += 256) spw2[i] = pos_w2[i];
    if (tid < 6) spb2[tid] = pos_b2[tid];
    __syncthreads();

    const int w = tid >> 5, lane = tid & 31;
    const int gw = blockIdx.x * 8 + w;      // 0..8191
    const int b = gw >> 11, n = gw & 2047;
    const int row = b * NN + n;

    for (int t = lane; t < 48; t += 32) soff[w][t] = g_off[row * 48 + t];
    if (lane < 16) snn[w][lane] = g_nn[row * 16 + lane];
    __syncwarp();

#pragma unroll 4
    for (int t = 0; t < 24; t++) {
        int idx = t * 32 + lane;
        int k = idx / 48, j = idx - k * 48;
        float o0 = soff[w][k * 3 + 0];
        float o1 = soff[w][k * 3 + 1];
        float o2 = soff[w][k * 3 + 2];
        float hv = __fmaf_rn(o0, spw1[j], spb1[j]);
        hv = __fmaf_rn(o1, spw1[48 + j], hv);
        hv = __fmaf_rn(o2, spw1[96 + j], hv);
        shid[w][k * 48 + j] = gelu_ref(hv);
    }
    __syncwarp();

#pragma unroll
    for (int t = 0; t < 3; t++) {
        int idx = t * 32 + lane;
        int k = idx / 6, h = idx - k * 6;
        float s = spb2[h];
#pragma unroll 8
        for (int j = 0; j < 48; j++)
            s = __fmaf_rn(shid[w][k * 48 + j], spw2[j * 6 + h], s);
        sbias[w][idx] = s;
    }
    __syncwarp();

    const float* qrow = g_qkv + (size_t)row * QKVN;
    float* orow = g_attn_out + (size_t)row * CC;
    const unsigned FULL = 0xffffffffu;

    for (int h = 0; h < HH; h++) {
        float qd = qrow[h * DD + lane];
        float lk = 0.f;
#pragma unroll
        for (int k = 0; k < KK; k++) {
            int nk = snn[w][k];
            float kv = g_qkv[(size_t)(b * NN + nk) * QKVN + CC + h * DD + lane];
            float p = qd * kv;
            p += __shfl_xor_sync(FULL, p, 16);
            p += __shfl_xor_sync(FULL, p, 8);
            p += __shfl_xor_sync(FULL, p, 4);
            p += __shfl_xor_sync(FULL, p, 2);
            p += __shfl_xor_sync(FULL, p, 1);
            if (lane == k) lk = p;
        }
        float logit = (lane < KK)
                      ? (lk * 0.17677669529663687f + sbias[w][lane * 6 + h])
                      : -1e30f;
        float m = logit;
        m = fmaxf(m, __shfl_xor_sync(FULL, m, 8));
        m = fmaxf(m, __shfl_xor_sync(FULL, m, 4));
        m = fmaxf(m, __shfl_xor_sync(FULL, m, 2));
        m = fmaxf(m, __shfl_xor_sync(FULL, m, 1));
        float e = (lane < KK) ? expf(logit - m) : 0.f;
        float s = e;
        s += __shfl_xor_sync(FULL, s, 8);
        s += __shfl_xor_sync(FULL, s, 4);
        s += __shfl_xor_sync(FULL, s, 2);
        s += __shfl_xor_sync(FULL, s, 1);
        float a = e / s;
        float od = 0.f;
#pragma unroll
        for (int k = 0; k < KK; k++) {
            float ak = __shfl_sync(FULL, a, k);
            int nk = snn[w][k];
            float vv = g_qkv[(size_t)(b * NN + nk) * QKVN + 2 * CC + h * DD + lane];
            od = __fmaf_rn(ak, vv, od);
        }
        orow[h * DD + lane] = od;
    }
}

// ---------------- launch (forked capture: qkv ∥ {h1→off→NN}) -------------------
extern "C" void kernel_launch(void* const* d_in, const int* in_sizes, int n_in,
                              void* d_out, int out_size) {
    const float* coords  = (const float*)d_in[0];
    const float* x       = (const float*)d_in[1];
    const float* qkv_w   = (const float*)d_in[2];
    const float* qkv_b   = (const float*)d_in[3];
    const float* proj_w  = (const float*)d_in[4];
    const float* proj_b  = (const float*)d_in[5];
    const float* off_w1  = (const float*)d_in[6];
    const float* off_b1  = (const float*)d_in[7];
    const float* off_w2  = (const float*)d_in[8];
    const float* off_b2  = (const float*)d_in[9];
    const float* pos_w1  = (const float*)d_in[10];
    const float* pos_b1  = (const float*)d_in[11];
    const float* pos_w2  = (const float*)d_in[12];
    const float* pos_b2  = (const float*)d_in[13];
    float* out = (float*)d_out;

    float *qkv_p, *h1_p, *off_p, *att_p;
    cudaGetSymbolAddress((void**)&qkv_p, g_qkv);
    cudaGetSymbolAddress((void**)&h1_p,  g_h1);
    cudaGetSymbolAddress((void**)&off_p, g_off);
    cudaGetSymbolAddress((void**)&att_p, g_attn_out);

    // Lazily-created side stream + fork/join events (host-side objects only).
    static cudaStream_t s_side = nullptr;
    static cudaEvent_t  s_fork = nullptr, s_join = nullptr;
    if (s_side == nullptr) {
        cudaStreamCreateWithFlags(&s_side, cudaStreamNonBlocking);
        cudaEventCreateWithFlags(&s_fork, cudaEventDisableTiming);
        cudaEventCreateWithFlags(&s_join, cudaEventDisableTiming);
    }

    // fork: side stream inherits capture state from the main (default) stream
    cudaEventRecord(s_fork, (cudaStream_t)0);
    cudaStreamWaitEvent(s_side, s_fork, 0);

    // -- branch B (side stream): qkv = x @ qkv_w + qkv_b   [8192,576]
    gemm128_kernel<false><<<dim3(QKVN / 64, ROWS / 128), 256, 0, s_side>>>(
        x, qkv_w, qkv_b, qkv_p, QKVN, CC);

    // -- branch A (main stream): offset net + NN
    // h1 = gelu(x @ off_w1 + off_b1)   [8192,96]
    gemm128_kernel<true><<<dim3(2, ROWS / 128), 256>>>(
        x, off_w1, off_b1, h1_p, CH, CC);
    // offsets = h1 @ off_w2 + off_b2   [8192,48]
    gemm_bias_kernel<false><<<dim3(1, ROWS / 64), 256>>>(
        h1_p, off_w2, off_b2, off_p, ROWS, 3 * KK, CH);
    // nearest-neighbor argmin (512 threads: 16 warps/SM)
    nn_kernel<<<dim3(38, BB), 512>>>(coords);

    // join: attn needs qkv (branch B) and NN (branch A)
    cudaEventRecord(s_join, s_side);
    cudaStreamWaitEvent((cudaStream_t)0, s_join, 0);

    // attention + positional bias
    attn_kernel<<<ROWS / 8, 256>>>(pos_w1, pos_b1, pos_w2, pos_b2);

    // out = attn_out @ proj_w + proj_b   [8192,192]
    gemm128_kernel<false><<<dim3(CC / 64, ROWS / 128), 256>>>(
        att_p, proj_w, proj_b, out, CC, CC);
}